// round 5
// baseline (speedup 1.0000x reference)
#include <cuda_runtime.h>
#include <cuda_bf16.h>
#include <cstdint>

#define N_Q    4096
#define N_R    65536
#define DIM    512
#define K_TOP  16

#define BM     128
#define BN     128
#define BK     64
#define NSPLIT 64
#define CHUNK  (N_R / NSPLIT)   // 1024
#define NT     (CHUNK / BN)     // 8
#define NKT    (DIM / BK)       // 8
#define TOT    (NT * NKT)       // 64

#define APITCH    144           // bytes per smem row (128 data + 16 pad)
#define STG       (BM * APITCH) // 18432
#define SC_OFF    (4 * STG)     // 73728
#define SPITCH    130
#define SMEM_TOTAL (SC_OFF + 64 * SPITCH * 4)   // 107008

// ---------------- scratch ----------------
__device__ __nv_bfloat16 g_xb[(size_t)N_Q * DIM];              // 4 MB
__device__ __nv_bfloat16 g_rb[(size_t)N_R * DIM];              // 64 MB
__device__ float         g_cand[(size_t)N_Q * NSPLIT * K_TOP]; // 16 MB

// ---------------- helpers ----------------
__device__ __forceinline__ uint32_t smem_u32(const void* p) {
    uint32_t a;
    asm("{ .reg .u64 t; cvta.to.shared.u64 t, %1; cvt.u32.u64 %0, t; }" : "=r"(a) : "l"(p));
    return a;
}
__device__ __forceinline__ void cp_async16(uint32_t dst, const void* src) {
    asm volatile("cp.async.cg.shared.global [%0], [%1], 16;\n" :: "r"(dst), "l"(src));
}
__device__ __forceinline__ void cp_commit() { asm volatile("cp.async.commit_group;\n" ::: "memory"); }
__device__ __forceinline__ void cp_wait_all() { asm volatile("cp.async.wait_group 0;\n" ::: "memory"); }

__device__ __forceinline__ void mma_bf16(float* c, const uint32_t* a, const uint32_t* b) {
    asm volatile(
        "mma.sync.aligned.m16n8k16.row.col.f32.bf16.bf16.f32 "
        "{%0,%1,%2,%3}, {%4,%5,%6,%7}, {%8,%9}, {%0,%1,%2,%3};\n"
        : "+f"(c[0]), "+f"(c[1]), "+f"(c[2]), "+f"(c[3])
        : "r"(a[0]), "r"(a[1]), "r"(a[2]), "r"(a[3]),
          "r"(b[0]), "r"(b[1]));
}
#define LDSM4(r0, r1, r2, r3, addr) \
    asm volatile("ldmatrix.sync.aligned.m8n8.x4.shared.b16 {%0,%1,%2,%3}, [%4];" \
                 : "=r"(r0), "=r"(r1), "=r"(r2), "=r"(r3) : "r"(addr))

// ---------------- prep: normalize x -> bf16 ----------------
__global__ void prep_x_kernel(const float* __restrict__ x) {
    int row = blockIdx.x;
    int t = threadIdx.x;
    const float* xr = x + (size_t)row * DIM;
    float v[4];
    float ss = 0.f;
#pragma unroll
    for (int i = 0; i < 4; ++i) { v[i] = xr[i * 128 + t]; ss += v[i] * v[i]; }
#pragma unroll
    for (int o = 16; o > 0; o >>= 1) ss += __shfl_xor_sync(0xffffffffu, ss, o);
    __shared__ float red[4];
    if ((t & 31) == 0) red[t >> 5] = ss;
    __syncthreads();
    float tot = red[0] + red[1] + red[2] + red[3];
    float scale = 1.0f / fmaxf(sqrtf(tot), 1e-12f);
#pragma unroll
    for (int i = 0; i < 4; ++i)
        g_xb[(size_t)row * DIM + i * 128 + t] = __float2bfloat16(v[i] * scale);
}

// ---------------- prep: refs fp32 -> bf16 ----------------
__global__ void conv_refs_kernel(const float* __restrict__ r) {
    size_t total4 = (size_t)N_R * DIM / 4;
    const float4* r4 = (const float4*)r;
    __nv_bfloat162* out2 = (__nv_bfloat162*)g_rb;
    for (size_t i = (size_t)blockIdx.x * blockDim.x + threadIdx.x; i < total4;
         i += (size_t)gridDim.x * blockDim.x) {
        float4 f = r4[i];
        out2[i * 2]     = __floats2bfloat162_rn(f.x, f.y);
        out2[i * 2 + 1] = __floats2bfloat162_rn(f.z, f.w);
    }
}

// ---------------- stage loader: A[128][64] + B[128][64] bf16 ----------------
__device__ __forceinline__ void issue_stage(uint32_t sb, int buf, int j,
                                            const __nv_bfloat16* Ag,
                                            const __nv_bfloat16* Bg, int tid) {
    int nt = j >> 3;
    int kof = (j & 7) * BK;
    uint32_t abase = sb + buf * STG;
    uint32_t bbase = sb + 2 * STG + buf * STG;
    const __nv_bfloat16* Bt = Bg + (size_t)nt * BN * DIM;
#pragma unroll
    for (int h = 0; h < 4; ++h) {
        int ch = tid + h * 256;     // 0..1023
        int row = ch >> 3;
        int c = ch & 7;
        cp_async16(abase + row * APITCH + c * 16,
                   Ag + (size_t)row * DIM + kof + c * 8);
        cp_async16(bbase + row * APITCH + c * 16,
                   Bt + (size_t)row * DIM + kof + c * 8);
    }
}

// ---------------- fused GEMM (ldmatrix + mma.sync) + top-16 ----------------
__global__ __launch_bounds__(256, 2) void fused_gemm_topk_kernel() {
    extern __shared__ uint8_t smem[];
    uint32_t sb = smem_u32(smem);
    float* sc = (float*)(smem + SC_OFF);

    int tid = threadIdx.x;
    int lane = tid & 31, warp = tid >> 5;
    int m0 = blockIdx.x * BM;
    int n0 = blockIdx.y * CHUNK;
    const __nv_bfloat16* Ag = g_xb + (size_t)m0 * DIM;
    const __nv_bfloat16* Bg = g_rb + (size_t)n0 * DIM;

    int wphase = warp >> 2;        // 0: rows 0-63, 1: rows 64-127
    int wm = wphase * 64;
    int wn = (warp & 3) * 32;
    int g = lane >> 2, q = lane & 3;

    // ldmatrix per-lane offsets
    uint32_t aoff = (uint32_t)((lane & 15) * APITCH + (lane >> 4) * 16);
    uint32_t boff = (uint32_t)((((lane >> 4) * 8) + (lane & 7)) * APITCH +
                               ((lane >> 3) & 1) * 16);

    // this thread owns query row (tid>>1), col-half (tid&1); active scan phase:
    int myrow = tid >> 1;          // 0..127
    int myphase = myrow >> 6;      // 0 or 1
    int lrow = myrow & 63;

    float t16[K_TOP];
#pragma unroll
    for (int j = 0; j < K_TOP; ++j) t16[j] = -1e30f;

    float acc[16][4];
#pragma unroll
    for (int i = 0; i < 16; ++i)
#pragma unroll
        for (int j = 0; j < 4; ++j) acc[i][j] = 0.f;

    // prologue
    issue_stage(sb, 0, 0, Ag, Bg, tid);
    cp_commit();

    int it = 0;
    for (int nt = 0; nt < NT; ++nt) {
        for (int kt = 0; kt < NKT; ++kt) {
            cp_wait_all();
            __syncthreads();
            if (it + 1 < TOT) {
                issue_stage(sb, (it + 1) & 1, it + 1, Ag, Bg, tid);
                cp_commit();
            }
            int buf = it & 1;
            uint32_t abase = sb + buf * STG;
            uint32_t bbase = sb + 2 * STG + buf * STG;
#pragma unroll
            for (int kk = 0; kk < 4; ++kk) {
                uint32_t af[4][4], bf2[4][2];
#pragma unroll
                for (int mf = 0; mf < 4; ++mf) {
                    uint32_t ad = abase + (wm + mf * 16) * APITCH + kk * 32 + aoff;
                    LDSM4(af[mf][0], af[mf][1], af[mf][2], af[mf][3], ad);
                }
#pragma unroll
                for (int pr = 0; pr < 2; ++pr) {
                    uint32_t bd = bbase + (wn + pr * 16) * APITCH + kk * 32 + boff;
                    LDSM4(bf2[pr * 2][0], bf2[pr * 2][1],
                          bf2[pr * 2 + 1][0], bf2[pr * 2 + 1][1], bd);
                }
#pragma unroll
                for (int mf = 0; mf < 4; ++mf)
#pragma unroll
                    for (int nf = 0; nf < 4; ++nf)
                        mma_bf16(acc[mf * 4 + nf], af[mf], bf2[nf]);
            }
            ++it;
        }

        // epilogue: two phases (rows 0-63 by warps 0-3, rows 64-127 by warps 4-7)
#pragma unroll
        for (int p = 0; p < 2; ++p) {
            __syncthreads();
            if (wphase == p) {
#pragma unroll
                for (int mf = 0; mf < 4; ++mf) {
#pragma unroll
                    for (int nf = 0; nf < 4; ++nf) {
                        int r0 = mf * 16 + g;             // local row 0..63
                        int c0 = wn + nf * 8 + q * 2;
                        sc[r0 * SPITCH + c0]           = acc[mf * 4 + nf][0];
                        sc[r0 * SPITCH + c0 + 1]       = acc[mf * 4 + nf][1];
                        sc[(r0 + 8) * SPITCH + c0]     = acc[mf * 4 + nf][2];
                        sc[(r0 + 8) * SPITCH + c0 + 1] = acc[mf * 4 + nf][3];
                        acc[mf * 4 + nf][0] = 0.f; acc[mf * 4 + nf][1] = 0.f;
                        acc[mf * 4 + nf][2] = 0.f; acc[mf * 4 + nf][3] = 0.f;
                    }
                }
            }
            __syncthreads();
            if (myphase == p) {
                const float* rowp = sc + lrow * SPITCH + (tid & 1) * 64;
                float th = t16[K_TOP - 1];
#pragma unroll 8
                for (int j = 0; j < 64; ++j) {
                    float v = rowp[j];
                    if (v > th) {
                        t16[K_TOP - 1] = v;
#pragma unroll
                        for (int pp = K_TOP - 1; pp > 0; --pp) {
                            float a = t16[pp - 1], bb = t16[pp];
                            t16[pp - 1] = fmaxf(a, bb);
                            t16[pp]     = fminf(a, bb);
                        }
                        th = t16[K_TOP - 1];
                    }
                }
            }
        }
        __syncthreads();
    }

    // pair-merge col-halves, write candidates
    float* lists = sc;   // 256*16 floats = 16 KB, fits
#pragma unroll
    for (int j = 0; j < K_TOP; ++j) lists[tid * K_TOP + j] = t16[j];
    __syncthreads();

    if ((tid & 1) == 0) {
        const float* a = &lists[tid * K_TOP];
        const float* b = &lists[(tid + 1) * K_TOP];
        float m[K_TOP];
        int ia = 0, ib = 0;
#pragma unroll
        for (int j = 0; j < K_TOP; ++j) {
            float av = a[ia], bv = b[ib];
            if (av >= bv) { m[j] = av; ++ia; }
            else          { m[j] = bv; ++ib; }
        }
        float* outp = g_cand + ((size_t)(m0 + myrow) * NSPLIT + blockIdx.y) * K_TOP;
#pragma unroll
        for (int j = 0; j < K_TOP; ++j) outp[j] = m[j];
    }
}

// ---------------- final merge + weights ----------------
__global__ __launch_bounds__(NSPLIT) void merge_kernel(float* __restrict__ out) {
    int qy = blockIdx.x;
    int s = threadIdx.x;   // 0..63
    __shared__ float sm[NSPLIT * K_TOP];
    const float* cp = g_cand + ((size_t)qy * NSPLIT + s) * K_TOP;
#pragma unroll
    for (int j = 0; j < K_TOP; ++j) sm[s * K_TOP + j] = cp[j];
    __syncthreads();

    for (int half = NSPLIT / 2; half >= 1; half >>= 1) {
        if (s < half) {
            float* a = &sm[s * K_TOP];
            float* b = &sm[(s + half) * K_TOP];
            float m[K_TOP];
            int ia = 0, ib = 0;
#pragma unroll
            for (int j = 0; j < K_TOP; ++j) {
                float av = a[ia], bv = b[ib];
                if (av >= bv) { m[j] = av; ++ia; }
                else          { m[j] = bv; ++ib; }
            }
#pragma unroll
            for (int j = 0; j < K_TOP; ++j) a[j] = m[j];
        }
        __syncthreads();
    }

    if (s == 0) {
        float w[K_TOP];
        float ssum = 0.f;
#pragma unroll
        for (int j = 0; j < K_TOP; ++j) {
            float d2 = fmaxf(2.0f - 2.0f * sm[j], 1e-12f);
            w[j] = expf(-sqrtf(d2));
            ssum += w[j];
        }
        float inv = 1.0f / fmaxf(ssum, 1e-12f);
#pragma unroll
        for (int j = 0; j < K_TOP; ++j)
            out[(size_t)qy * K_TOP + j] = w[j] * inv;
    }
}

// ---------------- launch ----------------
extern "C" void kernel_launch(void* const* d_in, const int* in_sizes, int n_in,
                              void* d_out, int out_size) {
    const float* x    = (const float*)d_in[0];
    const float* refs = (const float*)d_in[1];
    float* out = (float*)d_out;

    static bool attr_set = false;
    if (!attr_set) {
        cudaFuncSetAttribute(fused_gemm_topk_kernel,
                             cudaFuncAttributeMaxDynamicSharedMemorySize, SMEM_TOTAL);
        attr_set = true;
    }

    prep_x_kernel<<<N_Q, 128>>>(x);
    conv_refs_kernel<<<16384, 256>>>(refs);
    fused_gemm_topk_kernel<<<dim3(N_Q / BM, NSPLIT), 256, SMEM_TOTAL>>>();
    merge_kernel<<<N_Q, NSPLIT>>>(out);
}